// round 1
// baseline (speedup 1.0000x reference)
#include <cuda_runtime.h>

#define DIM 768
#define NH 12
#define HD 64
#define BATCH 2
#define SEQ 2048
#define ROWS (BATCH*SEQ)      // 4096
#define SCALE 0.125f          // 1/sqrt(64)
#define LN_EPS 1e-5f

// ---------------- scratch (device globals; no allocation allowed) ----------------
__device__ float g_xn[ROWS*DIM];                 // layernorm output  [4096,768]
__device__ float g_q [BATCH*NH*HD*SEQ];          // Q  [bh][d][n]  (d-major)
__device__ float g_k [BATCH*NH*HD*SEQ];          // K  [bh][d][n]  (d-major)
__device__ float g_v [BATCH*NH*SEQ*HD];          // V  [bh][n][d]
__device__ float g_att[ROWS*DIM];                // attention output [4096,768]

// ---------------- LayerNorm: one block per row of 768 ----------------
__global__ void ln_kernel(const float* __restrict__ x,
                          const float* __restrict__ gamma,
                          const float* __restrict__ beta) {
    int row = blockIdx.x;
    const float* xr = x + (size_t)row * DIM;
    int t = threadIdx.x;                  // 256 threads, 3 elems each
    float v0 = xr[t], v1 = xr[t+256], v2 = xr[t+512];
    __shared__ float red[8];

    float s = v0 + v1 + v2;
    #pragma unroll
    for (int o = 16; o > 0; o >>= 1) s += __shfl_xor_sync(0xffffffffu, s, o);
    if ((t & 31) == 0) red[t >> 5] = s;
    __syncthreads();
    if (t < 8) {
        float r = red[t];
        #pragma unroll
        for (int o = 4; o > 0; o >>= 1) r += __shfl_xor_sync(0xffu, r, o);
        if (t == 0) red[0] = r;
    }
    __syncthreads();
    float mean = red[0] * (1.0f / DIM);
    float d0 = v0 - mean, d1 = v1 - mean, d2 = v2 - mean;
    __syncthreads();

    float ss = d0*d0 + d1*d1 + d2*d2;
    #pragma unroll
    for (int o = 16; o > 0; o >>= 1) ss += __shfl_xor_sync(0xffffffffu, ss, o);
    if ((t & 31) == 0) red[t >> 5] = ss;
    __syncthreads();
    if (t < 8) {
        float r = red[t];
        #pragma unroll
        for (int o = 4; o > 0; o >>= 1) r += __shfl_xor_sync(0xffu, r, o);
        if (t == 0) red[0] = r;
    }
    __syncthreads();
    float rstd = rsqrtf(red[0] * (1.0f / DIM) + LN_EPS);

    float* o = g_xn + (size_t)row * DIM;
    o[t]     = d0 * rstd * gamma[t]     + beta[t];
    o[t+256] = d1 * rstd * gamma[t+256] + beta[t+256];
    o[t+512] = d2 * rstd * gamma[t+512] + beta[t+512];
}

// ---------------- 128x128x16 fp32 SIMT GEMM, 256 threads, 8x8 per thread ----------------
// MODE 1: A = g_xn, epilogue scatters into g_q/g_k/g_v head layouts (+ bias)
// MODE 0: A = g_att, epilogue writes C row-major (+ bias)
template<int MODE>
__global__ void __launch_bounds__(256, 2)
gemm_kernel(const float* __restrict__ Bmat, const float* __restrict__ bias,
            float* __restrict__ C, int Ncols) {
    const int K = DIM;
    const float* A = (MODE == 1) ? g_xn : g_att;

    __shared__ float As[16][128];   // transposed: As[k][m]
    __shared__ float Bs[16][128];   // Bs[k][n]

    int tid = threadIdx.x;
    int tx = tid & 15, ty = tid >> 4;
    int m0 = blockIdx.y * 128;
    int n0 = blockIdx.x * 128;

    float acc[8][8];
    #pragma unroll
    for (int i = 0; i < 8; i++)
        #pragma unroll
        for (int j = 0; j < 8; j++) acc[i][j] = 0.0f;

    for (int k0 = 0; k0 < K; k0 += 16) {
        #pragma unroll
        for (int l = 0; l < 2; l++) {
            int idx = tid + l*256;
            int m = idx >> 2;            // 0..127
            int kf = idx & 3;            // 0..3 (float4 along K)
            float4 a = *(const float4*)(A + (size_t)(m0+m)*K + k0 + kf*4);
            As[kf*4+0][m] = a.x; As[kf*4+1][m] = a.y;
            As[kf*4+2][m] = a.z; As[kf*4+3][m] = a.w;
        }
        #pragma unroll
        for (int l = 0; l < 2; l++) {
            int idx = tid + l*256;
            int kr = idx >> 5;           // 0..15
            int nf = idx & 31;           // float4 along N
            *(float4*)&Bs[kr][nf*4] =
                *(const float4*)(Bmat + (size_t)(k0+kr)*Ncols + n0 + nf*4);
        }
        __syncthreads();

        #pragma unroll
        for (int kk = 0; kk < 16; kk++) {
            float a[8], b[8];
            *(float4*)&a[0] = *(float4*)&As[kk][ty*8];
            *(float4*)&a[4] = *(float4*)&As[kk][ty*8+4];
            *(float4*)&b[0] = *(float4*)&Bs[kk][tx*8];
            *(float4*)&b[4] = *(float4*)&Bs[kk][tx*8+4];
            #pragma unroll
            for (int i = 0; i < 8; i++)
                #pragma unroll
                for (int j = 0; j < 8; j++)
                    acc[i][j] = fmaf(a[i], b[j], acc[i][j]);
        }
        __syncthreads();
    }

    if (MODE == 0) {
        #pragma unroll
        for (int i = 0; i < 8; i++) {
            int r = m0 + ty*8 + i;
            #pragma unroll
            for (int j = 0; j < 8; j++) {
                int c = n0 + tx*8 + j;
                C[(size_t)r*Ncols + c] = acc[i][j] + bias[c];
            }
        }
    } else {
        #pragma unroll
        for (int j = 0; j < 8; j++) {
            int c = n0 + tx*8 + j;
            int which = c / DIM;
            int cc = c - which*DIM;
            int h = cc >> 6, dd = cc & 63;
            float bv = bias[c];
            #pragma unroll
            for (int i = 0; i < 8; i++) {
                int r = m0 + ty*8 + i;
                int b = r >> 11, n = r & 2047;
                int bh = b*NH + h;
                float val = acc[i][j] + bv;
                if (which == 0)      g_q[((size_t)(bh*HD + dd) << 11) + n] = val;
                else if (which == 1) g_k[((size_t)(bh*HD + dd) << 11) + n] = val;
                else                 g_v[(size_t)(bh*SEQ + n)*HD + dd]     = val;
            }
        }
    }
}

// ---------------- flash attention: 64x64 tiles, fp32, online softmax ----------------
// grid: (SEQ/64 q-tiles, B*H), 256 threads (16x16, 4x4 per thread)
#define AST 68   // padded smem stride
__global__ void __launch_bounds__(256) attn_kernel() {
    extern __shared__ float sm[];
    float* Qs = sm;               // [d][q]  64 x AST
    float* Ks = Qs + 64*AST;      // [d][j]
    float* Vs = Ks + 64*AST;      // [j][c]
    float* Ps = Vs + 64*AST;      // [j][q]  (P transposed)

    int qt = blockIdx.x, bh = blockIdx.y;
    const float* Qg = g_q + (size_t)bh * HD * SEQ;
    const float* Kg = g_k + (size_t)bh * HD * SEQ;
    const float* Vg = g_v + (size_t)bh * SEQ * HD;

    int tid = threadIdx.x;
    int tx = tid & 15, ty = tid >> 4;
    int lr = tid >> 2;            // load row 0..63
    int lf = tid & 3;             // 4 threads per row

    // load Q tile (pre-scaled)
    #pragma unroll
    for (int i = 0; i < 4; i++) {
        int g = lf + 4*i;
        float4 v = *(const float4*)(Qg + (size_t)lr*SEQ + qt*64 + g*4);
        v.x *= SCALE; v.y *= SCALE; v.z *= SCALE; v.w *= SCALE;
        *(float4*)&Qs[lr*AST + g*4] = v;
    }

    float m_i[4], l_i[4], O[4][4];
    #pragma unroll
    for (int i = 0; i < 4; i++) {
        m_i[i] = -1e30f; l_i[i] = 0.0f;
        #pragma unroll
        for (int c = 0; c < 4; c++) O[i][c] = 0.0f;
    }

    for (int kt = 0; kt < SEQ/64; kt++) {
        __syncthreads();   // prev iter done with Ks/Vs/Ps; Q visible on iter 0
        #pragma unroll
        for (int i = 0; i < 4; i++) {
            int g = lf + 4*i;
            *(float4*)&Ks[lr*AST + g*4] =
                *(const float4*)(Kg + (size_t)lr*SEQ + kt*64 + g*4);
            *(float4*)&Vs[lr*AST + g*4] =
                *(const float4*)(Vg + (size_t)(kt*64 + lr)*HD + g*4);
        }
        __syncthreads();

        // S = (Q*scale) K^T  : reduce over d
        float s[4][4];
        #pragma unroll
        for (int i = 0; i < 4; i++)
            #pragma unroll
            for (int j = 0; j < 4; j++) s[i][j] = 0.0f;
        #pragma unroll 8
        for (int d = 0; d < 64; d++) {
            float4 q = *(float4*)&Qs[d*AST + ty*4];
            float4 k = *(float4*)&Ks[d*AST + tx*4];
            float qa[4] = {q.x,q.y,q.z,q.w};
            float ka[4] = {k.x,k.y,k.z,k.w};
            #pragma unroll
            for (int i = 0; i < 4; i++)
                #pragma unroll
                for (int j = 0; j < 4; j++)
                    s[i][j] = fmaf(qa[i], ka[j], s[i][j]);
        }

        // online softmax per q-row (16 threads share a row; contiguous half-warp)
        #pragma unroll
        for (int i = 0; i < 4; i++) {
            float rm = fmaxf(fmaxf(s[i][0], s[i][1]), fmaxf(s[i][2], s[i][3]));
            #pragma unroll
            for (int o = 1; o < 16; o <<= 1)
                rm = fmaxf(rm, __shfl_xor_sync(0xffffffffu, rm, o));
            float mnew = fmaxf(m_i[i], rm);
            float alpha = __expf(m_i[i] - mnew);
            float rs = 0.0f;
            #pragma unroll
            for (int j = 0; j < 4; j++) {
                float p = __expf(s[i][j] - mnew);
                s[i][j] = p; rs += p;
            }
            #pragma unroll
            for (int o = 1; o < 16; o <<= 1)
                rs += __shfl_xor_sync(0xffffffffu, rs, o);
            l_i[i] = l_i[i]*alpha + rs;
            m_i[i] = mnew;
            #pragma unroll
            for (int c = 0; c < 4; c++) O[i][c] *= alpha;
        }

        // store P transposed: Ps[j][q]
        #pragma unroll
        for (int jj = 0; jj < 4; jj++) {
            float4 p = make_float4(s[0][jj], s[1][jj], s[2][jj], s[3][jj]);
            *(float4*)&Ps[(tx*4 + jj)*AST + ty*4] = p;
        }
        __syncthreads();

        // O += P V : reduce over j
        #pragma unroll 8
        for (int j = 0; j < 64; j++) {
            float4 p = *(float4*)&Ps[j*AST + ty*4];
            float4 v = *(float4*)&Vs[j*AST + tx*4];
            float pa[4] = {p.x,p.y,p.z,p.w};
            float va[4] = {v.x,v.y,v.z,v.w};
            #pragma unroll
            for (int i = 0; i < 4; i++)
                #pragma unroll
                for (int c = 0; c < 4; c++)
                    O[i][c] = fmaf(pa[i], va[c], O[i][c]);
        }
    }

    // epilogue: normalize and write [B,N,D]
    int b = bh / NH, h = bh - b*NH;
    #pragma unroll
    for (int i = 0; i < 4; i++) {
        float inv = 1.0f / l_i[i];
        int n = qt*64 + ty*4 + i;
        float4 o = make_float4(O[i][0]*inv, O[i][1]*inv, O[i][2]*inv, O[i][3]*inv);
        *(float4*)(g_att + (size_t)(b*SEQ + n)*DIM + h*HD + tx*4) = o;
    }
}

// ---------------- launch ----------------
extern "C" void kernel_launch(void* const* d_in, const int* in_sizes, int n_in,
                              void* d_out, int out_size) {
    const float* x     = (const float*)d_in[0];
    const float* gamma = (const float*)d_in[1];
    const float* beta  = (const float*)d_in[2];
    const float* Wqkv  = (const float*)d_in[3];
    const float* bqkv  = (const float*)d_in[4];
    const float* Wout  = (const float*)d_in[5];
    const float* bout  = (const float*)d_in[6];
    float* out = (float*)d_out;

    ln_kernel<<<ROWS, 256>>>(x, gamma, beta);

    gemm_kernel<1><<<dim3((3*DIM)/128, ROWS/128), 256>>>(Wqkv, bqkv, nullptr, 3*DIM);

    const int attn_smem = 4 * 64 * AST * (int)sizeof(float);  // 69632 B
    cudaFuncSetAttribute(attn_kernel, cudaFuncAttributeMaxDynamicSharedMemorySize, attn_smem);
    attn_kernel<<<dim3(SEQ/64, BATCH*NH), 256, attn_smem>>>();

    gemm_kernel<0><<<dim3(DIM/128, ROWS/128), 256>>>(Wout, bout, out, DIM);
}

// round 2
// speedup vs baseline: 3.0992x; 3.0992x over previous
#include <cuda_runtime.h>

#define DIM 768
#define NH 12
#define HD 64
#define BATCH 2
#define SEQ 2048
#define ROWS (BATCH*SEQ)      // 4096
#define SCALE 0.125f
#define LN_EPS 1e-5f

// ---------------- scratch ----------------
__device__ float g_xn[ROWS*DIM];
__device__ float g_q [BATCH*NH*SEQ*HD];   // [bh][n][d]
__device__ float g_k [BATCH*NH*SEQ*HD];   // [bh][n][d]
__device__ float g_v [BATCH*NH*SEQ*HD];   // [bh][n][d]
__device__ float g_att[ROWS*DIM];

// ---------------- tf32 helpers ----------------
__device__ __forceinline__ unsigned f2tf(float x) {
    unsigned u; asm("cvt.rna.tf32.f32 %0, %1;" : "=r"(u) : "f"(x)); return u;
}
__device__ __forceinline__ float f2tff(float x) { return __uint_as_float(f2tf(x)); }

__device__ __forceinline__ void mma8(float* c, const unsigned* a, const unsigned* b) {
    asm volatile("mma.sync.aligned.m16n8k8.row.col.f32.tf32.tf32.f32 "
        "{%0,%1,%2,%3}, {%4,%5,%6,%7}, {%8,%9}, {%0,%1,%2,%3};"
        : "+f"(c[0]), "+f"(c[1]), "+f"(c[2]), "+f"(c[3])
        : "r"(a[0]), "r"(a[1]), "r"(a[2]), "r"(a[3]), "r"(b[0]), "r"(b[1]));
}

// ---------------- LayerNorm ----------------
__global__ void ln_kernel(const float* __restrict__ x,
                          const float* __restrict__ gamma,
                          const float* __restrict__ beta) {
    int row = blockIdx.x;
    const float* xr = x + (size_t)row * DIM;
    int t = threadIdx.x;
    float v0 = xr[t], v1 = xr[t+256], v2 = xr[t+512];
    __shared__ float red[8];

    float s = v0 + v1 + v2;
    #pragma unroll
    for (int o = 16; o > 0; o >>= 1) s += __shfl_xor_sync(0xffffffffu, s, o);
    if ((t & 31) == 0) red[t >> 5] = s;
    __syncthreads();
    if (t < 8) {
        float r = red[t];
        #pragma unroll
        for (int o = 4; o > 0; o >>= 1) r += __shfl_xor_sync(0xffu, r, o);
        if (t == 0) red[0] = r;
    }
    __syncthreads();
    float mean = red[0] * (1.0f / DIM);
    float d0 = v0 - mean, d1 = v1 - mean, d2 = v2 - mean;
    __syncthreads();

    float ss = d0*d0 + d1*d1 + d2*d2;
    #pragma unroll
    for (int o = 16; o > 0; o >>= 1) ss += __shfl_xor_sync(0xffffffffu, ss, o);
    if ((t & 31) == 0) red[t >> 5] = ss;
    __syncthreads();
    if (t < 8) {
        float r = red[t];
        #pragma unroll
        for (int o = 4; o > 0; o >>= 1) r += __shfl_xor_sync(0xffu, r, o);
        if (t == 0) red[0] = r;
    }
    __syncthreads();
    float rstd = rsqrtf(red[0] * (1.0f / DIM) + LN_EPS);

    float* o = g_xn + (size_t)row * DIM;
    o[t]     = d0 * rstd * gamma[t]     + beta[t];
    o[t+256] = d1 * rstd * gamma[t+256] + beta[t+256];
    o[t+512] = d2 * rstd * gamma[t+512] + beta[t+512];
}

// ---------------- TF32 tensor-core GEMM: 128x128x32, 8 warps (64x32 each) ----------------
// MODE 1: A=g_xn, C scatters into g_q/g_k/g_v [bh][n][d] (+bias)
// MODE 0: A=g_att, C row-major (+bias)
template<int MODE>
__global__ void __launch_bounds__(256, 2)
gemm_kernel(const float* __restrict__ Bmat, const float* __restrict__ bias,
            float* __restrict__ C, int Ncols) {
    const float* A = (MODE == 1) ? g_xn : g_att;
    __shared__ __align__(16) float As[128][36];   // [m][k], frag banks 4g+t (distinct)
    __shared__ __align__(16) float Bs[32][136];   // [k][n], frag banks 8t+g (distinct)

    int tid = threadIdx.x;
    int wid = tid >> 5, lane = tid & 31;
    int g = lane >> 2, t = lane & 3;
    int wm = (wid >> 2) * 64, wn = (wid & 3) * 32;
    int m0 = blockIdx.y * 128, n0 = blockIdx.x * 128;

    float acc[4][4][4];
    #pragma unroll
    for (int i = 0; i < 4; i++)
        #pragma unroll
        for (int j = 0; j < 4; j++)
            #pragma unroll
            for (int r = 0; r < 4; r++) acc[i][j][r] = 0.0f;

    for (int k0 = 0; k0 < DIM; k0 += 32) {
        #pragma unroll
        for (int l = 0; l < 4; l++) {
            int idx = tid + l*256;
            int row = idx >> 3, cf = idx & 7;
            float4 a = *(const float4*)(A + (size_t)(m0+row)*DIM + k0 + cf*4);
            As[row][cf*4+0] = f2tff(a.x); As[row][cf*4+1] = f2tff(a.y);
            As[row][cf*4+2] = f2tff(a.z); As[row][cf*4+3] = f2tff(a.w);
        }
        #pragma unroll
        for (int l = 0; l < 4; l++) {
            int idx = tid + l*256;
            int row = idx >> 5, cf = idx & 31;
            float4 b = *(const float4*)(Bmat + (size_t)(k0+row)*Ncols + n0 + cf*4);
            Bs[row][cf*4+0] = f2tff(b.x); Bs[row][cf*4+1] = f2tff(b.y);
            Bs[row][cf*4+2] = f2tff(b.z); Bs[row][cf*4+3] = f2tff(b.w);
        }
        __syncthreads();

        #pragma unroll
        for (int ks = 0; ks < 4; ks++) {
            int kb = ks*8;
            unsigned af[4][4], bf[4][2];
            #pragma unroll
            for (int i = 0; i < 4; i++) {
                int r = wm + i*16 + g;
                af[i][0] = __float_as_uint(As[r  ][kb+t  ]);
                af[i][1] = __float_as_uint(As[r+8][kb+t  ]);
                af[i][2] = __float_as_uint(As[r  ][kb+t+4]);
                af[i][3] = __float_as_uint(As[r+8][kb+t+4]);
            }
            #pragma unroll
            for (int j = 0; j < 4; j++) {
                int c = wn + j*8 + g;
                bf[j][0] = __float_as_uint(Bs[kb+t  ][c]);
                bf[j][1] = __float_as_uint(Bs[kb+t+4][c]);
            }
            #pragma unroll
            for (int i = 0; i < 4; i++)
                #pragma unroll
                for (int j = 0; j < 4; j++)
                    mma8(acc[i][j], af[i], bf[j]);
        }
        __syncthreads();
    }

    // epilogue: C frag (g,2t),(g,2t+1),(g+8,2t),(g+8,2t+1)
    #pragma unroll
    for (int j = 0; j < 4; j++) {
        int c0 = n0 + wn + j*8 + 2*t;
        float b0 = bias[c0], b1 = bias[c0+1];
        if (MODE == 0) {
            #pragma unroll
            for (int i = 0; i < 4; i++) {
                int ra = m0 + wm + i*16 + g;
                float2 va = make_float2(acc[i][j][0] + b0, acc[i][j][1] + b1);
                float2 vb = make_float2(acc[i][j][2] + b0, acc[i][j][3] + b1);
                *(float2*)(C + (size_t)ra*Ncols + c0) = va;
                *(float2*)(C + (size_t)(ra+8)*Ncols + c0) = vb;
            }
        } else {
            int which = c0 / DIM;
            int cc = c0 - which*DIM;
            int h = cc >> 6, dd = cc & 63;
            float* dst = (which == 0) ? g_q : (which == 1) ? g_k : g_v;
            #pragma unroll
            for (int i = 0; i < 4; i++) {
                int ra = m0 + wm + i*16 + g;
                int bb = ra >> 11, n = ra & 2047;
                size_t base = ((size_t)((bb*NH + h)*SEQ + n))*HD + dd;
                float2 va = make_float2(acc[i][j][0] + b0, acc[i][j][1] + b1);
                float2 vb = make_float2(acc[i][j][2] + b0, acc[i][j][3] + b1);
                *(float2*)(dst + base) = va;
                *(float2*)(dst + base + (size_t)8*HD) = vb;
            }
        }
    }
}

// ---------------- TF32 flash attention: 128q x 64k tiles, 8 warps (16q x 64k each) ----------------
#define QST 68
#define KST 72
__global__ void __launch_bounds__(256, 2) attn_kernel() {
    extern __shared__ float sm[];
    float* Qs = sm;                    // [128][68], reused as Ps
    float* Ks = sm + 128*QST;          // [64][72]
    float* Vs = Ks + 64*KST;           // [64][72]

    int qt = blockIdx.x, bh = blockIdx.y;
    const float* Qg = g_q + (size_t)bh*SEQ*HD;
    const float* Kg = g_k + (size_t)bh*SEQ*HD;
    const float* Vg = g_v + (size_t)bh*SEQ*HD;

    int tid = threadIdx.x, wid = tid >> 5, lane = tid & 31;
    int g = lane >> 2, t = lane & 3;
    int r0 = wid*16 + g;

    // load Q tile (scaled, tf32)
    #pragma unroll
    for (int l = 0; l < 8; l++) {
        int idx = tid + l*256;
        int row = idx >> 4, cf = idx & 15;
        float4 q = *(const float4*)(Qg + ((size_t)(qt*128+row))*HD + cf*4);
        Qs[row*QST + cf*4+0] = f2tff(q.x * SCALE);
        Qs[row*QST + cf*4+1] = f2tff(q.y * SCALE);
        Qs[row*QST + cf*4+2] = f2tff(q.z * SCALE);
        Qs[row*QST + cf*4+3] = f2tff(q.w * SCALE);
    }
    __syncthreads();

    // Q A-fragments -> registers (reused across all k-tiles)
    unsigned qf[8][4];
    #pragma unroll
    for (int kk = 0; kk < 8; kk++) {
        qf[kk][0] = __float_as_uint(Qs[r0*QST + kk*8 + t]);
        qf[kk][1] = __float_as_uint(Qs[(r0+8)*QST + kk*8 + t]);
        qf[kk][2] = __float_as_uint(Qs[r0*QST + kk*8 + t + 4]);
        qf[kk][3] = __float_as_uint(Qs[(r0+8)*QST + kk*8 + t + 4]);
    }

    float mr0 = -1e30f, mr1 = -1e30f, lr0 = 0.0f, lr1 = 0.0f;
    float O[8][4];
    #pragma unroll
    for (int dt = 0; dt < 8; dt++)
        #pragma unroll
        for (int r = 0; r < 4; r++) O[dt][r] = 0.0f;

    for (int kt = 0; kt < SEQ/64; kt++) {
        __syncthreads();   // all warps done with Ks/Vs (and Qs frag reads on iter 0)
        #pragma unroll
        for (int l = 0; l < 4; l++) {
            int idx = tid + l*256;
            int row = idx >> 4, cf = idx & 15;
            float4 k4 = *(const float4*)(Kg + ((size_t)(kt*64+row))*HD + cf*4);
            Ks[row*KST + cf*4+0] = f2tff(k4.x); Ks[row*KST + cf*4+1] = f2tff(k4.y);
            Ks[row*KST + cf*4+2] = f2tff(k4.z); Ks[row*KST + cf*4+3] = f2tff(k4.w);
            float4 v4 = *(const float4*)(Vg + ((size_t)(kt*64+row))*HD + cf*4);
            Vs[row*KST + cf*4+0] = f2tff(v4.x); Vs[row*KST + cf*4+1] = f2tff(v4.y);
            Vs[row*KST + cf*4+2] = f2tff(v4.z); Vs[row*KST + cf*4+3] = f2tff(v4.w);
        }
        __syncthreads();

        // S = Q K^T  (per warp 16x64)
        float s[8][4];
        #pragma unroll
        for (int nt = 0; nt < 8; nt++)
            #pragma unroll
            for (int r = 0; r < 4; r++) s[nt][r] = 0.0f;
        #pragma unroll
        for (int kk = 0; kk < 8; kk++) {
            #pragma unroll
            for (int nt = 0; nt < 8; nt++) {
                unsigned bf[2];
                bf[0] = __float_as_uint(Ks[(nt*8+g)*KST + kk*8 + t]);
                bf[1] = __float_as_uint(Ks[(nt*8+g)*KST + kk*8 + t + 4]);
                mma8(s[nt], qf[kk], bf);
            }
        }

        // online softmax: rows r0 (c0,c1) and r0+8 (c2,c3)
        float rm0 = -1e30f, rm1 = -1e30f;
        #pragma unroll
        for (int nt = 0; nt < 8; nt++) {
            rm0 = fmaxf(rm0, fmaxf(s[nt][0], s[nt][1]));
            rm1 = fmaxf(rm1, fmaxf(s[nt][2], s[nt][3]));
        }
        rm0 = fmaxf(rm0, __shfl_xor_sync(0xffffffffu, rm0, 1));
        rm0 = fmaxf(rm0, __shfl_xor_sync(0xffffffffu, rm0, 2));
        rm1 = fmaxf(rm1, __shfl_xor_sync(0xffffffffu, rm1, 1));
        rm1 = fmaxf(rm1, __shfl_xor_sync(0xffffffffu, rm1, 2));
        float mn0 = fmaxf(mr0, rm0), mn1 = fmaxf(mr1, rm1);
        float a0 = __expf(mr0 - mn0), a1 = __expf(mr1 - mn1);
        mr0 = mn0; mr1 = mn1;
        float rs0 = 0.0f, rs1 = 0.0f;
        #pragma unroll
        for (int nt = 0; nt < 8; nt++) {
            s[nt][0] = __expf(s[nt][0] - mn0); rs0 += s[nt][0];
            s[nt][1] = __expf(s[nt][1] - mn0); rs0 += s[nt][1];
            s[nt][2] = __expf(s[nt][2] - mn1); rs1 += s[nt][2];
            s[nt][3] = __expf(s[nt][3] - mn1); rs1 += s[nt][3];
        }
        rs0 += __shfl_xor_sync(0xffffffffu, rs0, 1);
        rs0 += __shfl_xor_sync(0xffffffffu, rs0, 2);
        rs1 += __shfl_xor_sync(0xffffffffu, rs1, 1);
        rs1 += __shfl_xor_sync(0xffffffffu, rs1, 2);
        lr0 = lr0*a0 + rs0; lr1 = lr1*a1 + rs1;
        #pragma unroll
        for (int dt = 0; dt < 8; dt++) {
            O[dt][0] *= a0; O[dt][1] *= a0;
            O[dt][2] *= a1; O[dt][3] *= a1;
        }

        // store P (tf32) into warp-private rows of Qs/Ps
        float* Ps = Qs;
        #pragma unroll
        for (int nt = 0; nt < 8; nt++) {
            float2 p0 = make_float2(f2tff(s[nt][0]), f2tff(s[nt][1]));
            float2 p1 = make_float2(f2tff(s[nt][2]), f2tff(s[nt][3]));
            *(float2*)&Ps[r0*QST + nt*8 + 2*t] = p0;
            *(float2*)&Ps[(r0+8)*QST + nt*8 + 2*t] = p1;
        }
        __syncwarp();

        // O += P V
        #pragma unroll
        for (int jj = 0; jj < 8; jj++) {
            unsigned af[4];
            af[0] = __float_as_uint(Ps[r0*QST + jj*8 + t]);
            af[1] = __float_as_uint(Ps[(r0+8)*QST + jj*8 + t]);
            af[2] = __float_as_uint(Ps[r0*QST + jj*8 + t + 4]);
            af[3] = __float_as_uint(Ps[(r0+8)*QST + jj*8 + t + 4]);
            #pragma unroll
            for (int dt = 0; dt < 8; dt++) {
                unsigned bf[2];
                bf[0] = __float_as_uint(Vs[(jj*8+t)*KST + dt*8 + g]);
                bf[1] = __float_as_uint(Vs[(jj*8+t+4)*KST + dt*8 + g]);
                mma8(O[dt], af, bf);
            }
        }
    }

    // epilogue: normalize, write [B,N,D]
    int b = bh / NH, h = bh - b*NH;
    float inv0 = 1.0f/lr0, inv1 = 1.0f/lr1;
    int n = qt*128 + r0;
    #pragma unroll
    for (int dt = 0; dt < 8; dt++) {
        int d = h*HD + dt*8 + 2*t;
        float2 va = make_float2(O[dt][0]*inv0, O[dt][1]*inv0);
        float2 vb = make_float2(O[dt][2]*inv1, O[dt][3]*inv1);
        *(float2*)(g_att + ((size_t)(b*SEQ + n))*DIM + d) = va;
        *(float2*)(g_att + ((size_t)(b*SEQ + n + 8))*DIM + d) = vb;
    }
}

// ---------------- launch ----------------
extern "C" void kernel_launch(void* const* d_in, const int* in_sizes, int n_in,
                              void* d_out, int out_size) {
    const float* x     = (const float*)d_in[0];
    const float* gamma = (const float*)d_in[1];
    const float* beta  = (const float*)d_in[2];
    const float* Wqkv  = (const float*)d_in[3];
    const float* bqkv  = (const float*)d_in[4];
    const float* Wout  = (const float*)d_in[5];
    const float* bout  = (const float*)d_in[6];
    float* out = (float*)d_out;

    ln_kernel<<<ROWS, 256>>>(x, gamma, beta);

    gemm_kernel<1><<<dim3((3*DIM)/128, ROWS/128), 256>>>(Wqkv, bqkv, nullptr, 3*DIM);

    const int attn_smem = (128*QST + 2*64*KST) * (int)sizeof(float);  // 71680 B
    cudaFuncSetAttribute(attn_kernel, cudaFuncAttributeMaxDynamicSharedMemorySize, attn_smem);
    attn_kernel<<<dim3(SEQ/128, BATCH*NH), 256, attn_smem>>>();

    gemm_kernel<0><<<dim3(DIM/128, ROWS/128), 256>>>(Wout, bout, out, DIM);
}

// round 3
// speedup vs baseline: 3.3562x; 1.0829x over previous
#include <cuda_runtime.h>

#define DIM 768
#define NH 12
#define HD 64
#define BATCH 2
#define SEQ 2048
#define ROWS (BATCH*SEQ)      // 4096
#define SCALE 0.125f
#define LN_EPS 1e-5f

// ---------------- scratch (tf32-rounded payloads) ----------------
__device__ float g_xn[ROWS*DIM];
__device__ float g_q [BATCH*NH*SEQ*HD];   // [bh][n][d], pre-scaled by SCALE
__device__ float g_k [BATCH*NH*SEQ*HD];
__device__ float g_v [BATCH*NH*SEQ*HD];
__device__ float g_att[ROWS*DIM];
__device__ float g_wq[DIM*3*DIM];         // tf32-rounded W_qkv
__device__ float g_wo[DIM*DIM];           // tf32-rounded W_out

// ---------------- helpers ----------------
__device__ __forceinline__ unsigned f2tf(float x) {
    unsigned u; asm("cvt.rna.tf32.f32 %0, %1;" : "=r"(u) : "f"(x)); return u;
}
__device__ __forceinline__ float f2tff(float x) { return __uint_as_float(f2tf(x)); }

__device__ __forceinline__ void mma8(float* c, const unsigned* a, const unsigned* b) {
    asm volatile("mma.sync.aligned.m16n8k8.row.col.f32.tf32.tf32.f32 "
        "{%0,%1,%2,%3}, {%4,%5,%6,%7}, {%8,%9}, {%0,%1,%2,%3};"
        : "+f"(c[0]), "+f"(c[1]), "+f"(c[2]), "+f"(c[3])
        : "r"(a[0]), "r"(a[1]), "r"(a[2]), "r"(a[3]), "r"(b[0]), "r"(b[1]));
}

__device__ __forceinline__ void cp16(float* dst, const float* src) {
    unsigned d = (unsigned)__cvta_generic_to_shared(dst);
    asm volatile("cp.async.cg.shared.global [%0], [%1], 16;" :: "r"(d), "l"(src));
}
#define CPCOMMIT  asm volatile("cp.async.commit_group;" ::: "memory")
#define CPWAIT0   asm volatile("cp.async.wait_group 0;"  ::: "memory")
#define CPWAIT1   asm volatile("cp.async.wait_group 1;"  ::: "memory")

// ---------------- weight pre-convert to tf32 ----------------
__global__ void wcvt_kernel(const float4* __restrict__ src, int n4, int which) {
    float4* dst = (float4*)(which ? g_wo : g_wq);
    int i = blockIdx.x * blockDim.x + threadIdx.x;
    if (i < n4) {
        float4 v = src[i];
        v.x = f2tff(v.x); v.y = f2tff(v.y); v.z = f2tff(v.z); v.w = f2tff(v.w);
        dst[i] = v;
    }
}

// ---------------- LayerNorm (tf32-rounded output) ----------------
__global__ void ln_kernel(const float* __restrict__ x,
                          const float* __restrict__ gamma,
                          const float* __restrict__ beta) {
    int row = blockIdx.x;
    const float* xr = x + (size_t)row * DIM;
    int t = threadIdx.x;
    float v0 = xr[t], v1 = xr[t+256], v2 = xr[t+512];
    __shared__ float red[8];

    float s = v0 + v1 + v2;
    #pragma unroll
    for (int o = 16; o > 0; o >>= 1) s += __shfl_xor_sync(0xffffffffu, s, o);
    if ((t & 31) == 0) red[t >> 5] = s;
    __syncthreads();
    if (t < 8) {
        float r = red[t];
        #pragma unroll
        for (int o = 4; o > 0; o >>= 1) r += __shfl_xor_sync(0xffu, r, o);
        if (t == 0) red[0] = r;
    }
    __syncthreads();
    float mean = red[0] * (1.0f / DIM);
    float d0 = v0 - mean, d1 = v1 - mean, d2 = v2 - mean;
    __syncthreads();

    float ss = d0*d0 + d1*d1 + d2*d2;
    #pragma unroll
    for (int o = 16; o > 0; o >>= 1) ss += __shfl_xor_sync(0xffffffffu, ss, o);
    if ((t & 31) == 0) red[t >> 5] = ss;
    __syncthreads();
    if (t < 8) {
        float r = red[t];
        #pragma unroll
        for (int o = 4; o > 0; o >>= 1) r += __shfl_xor_sync(0xffu, r, o);
        if (t == 0) red[0] = r;
    }
    __syncthreads();
    float rstd = rsqrtf(red[0] * (1.0f / DIM) + LN_EPS);

    float* o = g_xn + (size_t)row * DIM;
    o[t]     = f2tff(d0 * rstd * gamma[t]     + beta[t]);
    o[t+256] = f2tff(d1 * rstd * gamma[t+256] + beta[t+256]);
    o[t+512] = f2tff(d2 * rstd * gamma[t+512] + beta[t+512]);
}

// ---------------- TF32 GEMM: 128x128x32 tiles, 3-stage cp.async pipeline ----------------
// MODE 1: A=g_xn, B=g_wq, scatter into g_q/g_k/g_v (+bias, q scaled)
// MODE 0: A=g_att, B=g_wo, C row-major (+bias)
#define AS_STG (128*36)   // 4608 floats per stage
#define BS_STG (32*136)   // 4352 floats per stage
#define GEMM_SMEM ((3*AS_STG + 3*BS_STG)*4)

#define GEMM_PREFETCH(k0, st) do { \
    _Pragma("unroll") \
    for (int l = 0; l < 4; l++) { int idx = tid + l*256; int row = idx >> 3, cf = idx & 7; \
        cp16(Asb + (st)*AS_STG + row*36 + cf*4, A + (size_t)(m0+row)*DIM + (k0) + cf*4); } \
    _Pragma("unroll") \
    for (int l = 0; l < 4; l++) { int idx = tid + l*256; int row = idx >> 5, cf = idx & 31; \
        cp16(Bsb + (st)*BS_STG + row*136 + cf*4, Bm + (size_t)((k0)+row)*Ncols + n0 + cf*4); } \
} while (0)

template<int MODE>
__global__ void __launch_bounds__(256, 2)
gemm_kernel(const float* __restrict__ bias, float* __restrict__ C, int Ncols) {
    const float* A  = (MODE == 1) ? g_xn : g_att;
    const float* Bm = (MODE == 1) ? g_wq : g_wo;
    extern __shared__ __align__(16) float smg[];
    float* Asb = smg;
    float* Bsb = smg + 3*AS_STG;

    int tid = threadIdx.x;
    int wid = tid >> 5, lane = tid & 31;
    int g = lane >> 2, t = lane & 3;
    int wm = (wid >> 2) * 64, wn = (wid & 3) * 32;
    int m0 = blockIdx.y * 128, n0 = blockIdx.x * 128;

    float acc[4][4][4];
    #pragma unroll
    for (int i = 0; i < 4; i++)
        #pragma unroll
        for (int j = 0; j < 4; j++)
            #pragma unroll
            for (int r = 0; r < 4; r++) acc[i][j][r] = 0.0f;

    GEMM_PREFETCH(0, 0);  CPCOMMIT;
    GEMM_PREFETCH(32, 1); CPCOMMIT;

    const int NK = DIM/32;   // 24
    for (int kt = 0; kt < NK; kt++) {
        CPWAIT1;
        __syncthreads();
        if (kt + 2 < NK) { int pst = (kt+2) % 3; GEMM_PREFETCH((kt+2)*32, pst); }
        CPCOMMIT;   // empty group when no prefetch keeps accounting uniform

        int st = kt % 3;
        const float* Ast = Asb + st*AS_STG;
        const float* Bst = Bsb + st*BS_STG;

        #pragma unroll
        for (int ks = 0; ks < 4; ks++) {
            int kb = ks*8;
            unsigned af[4][4], bf[4][2];
            #pragma unroll
            for (int i = 0; i < 4; i++) {
                int r = wm + i*16 + g;
                af[i][0] = __float_as_uint(Ast[r*36     + kb+t  ]);
                af[i][1] = __float_as_uint(Ast[(r+8)*36 + kb+t  ]);
                af[i][2] = __float_as_uint(Ast[r*36     + kb+t+4]);
                af[i][3] = __float_as_uint(Ast[(r+8)*36 + kb+t+4]);
            }
            #pragma unroll
            for (int j = 0; j < 4; j++) {
                int c = wn + j*8 + g;
                bf[j][0] = __float_as_uint(Bst[(kb+t  )*136 + c]);
                bf[j][1] = __float_as_uint(Bst[(kb+t+4)*136 + c]);
            }
            #pragma unroll
            for (int i = 0; i < 4; i++)
                #pragma unroll
                for (int j = 0; j < 4; j++)
                    mma8(acc[i][j], af[i], bf[j]);
        }
        __syncthreads();
    }

    #pragma unroll
    for (int j = 0; j < 4; j++) {
        int c0 = n0 + wn + j*8 + 2*t;
        float b0 = bias[c0], b1 = bias[c0+1];
        if (MODE == 0) {
            #pragma unroll
            for (int i = 0; i < 4; i++) {
                int ra = m0 + wm + i*16 + g;
                float2 va = make_float2(acc[i][j][0] + b0, acc[i][j][1] + b1);
                float2 vb = make_float2(acc[i][j][2] + b0, acc[i][j][3] + b1);
                *(float2*)(C + (size_t)ra*Ncols + c0) = va;
                *(float2*)(C + (size_t)(ra+8)*Ncols + c0) = vb;
            }
        } else {
            int which = c0 / DIM;
            int cc = c0 - which*DIM;
            int h = cc >> 6, dd = cc & 63;
            float* dst = (which == 0) ? g_q : (which == 1) ? g_k : g_v;
            float mul = (which == 0) ? SCALE : 1.0f;
            #pragma unroll
            for (int i = 0; i < 4; i++) {
                int ra = m0 + wm + i*16 + g;
                int bb = ra >> 11, n = ra & 2047;
                size_t base = ((size_t)((bb*NH + h)*SEQ + n))*HD + dd;
                float2 va = make_float2(f2tff((acc[i][j][0] + b0)*mul),
                                        f2tff((acc[i][j][1] + b1)*mul));
                float2 vb = make_float2(f2tff((acc[i][j][2] + b0)*mul),
                                        f2tff((acc[i][j][3] + b1)*mul));
                *(float2*)(dst + base) = va;
                *(float2*)(dst + base + (size_t)8*HD) = vb;
            }
        }
    }
}

// ---------------- TF32 flash attention: 128q x 64k, 2-stage K/V pipeline ----------------
#define QST 68
#define KST 72
#define KV_STG (64*KST)   // 4608 floats per stage
#define ATTN_SMEM ((128*QST + 2*KV_STG*2)*4)

#define ATTN_PREFETCH(kt, st) do { \
    _Pragma("unroll") \
    for (int l = 0; l < 4; l++) { int idx = tid + l*256; int row = idx >> 4, cf = idx & 15; \
        cp16(Ksb + (st)*KV_STG + row*KST + cf*4, Kg + ((size_t)((kt)*64+row))*HD + cf*4); \
        cp16(Vsb + (st)*KV_STG + row*KST + cf*4, Vg + ((size_t)((kt)*64+row))*HD + cf*4); } \
} while (0)

__global__ void __launch_bounds__(256, 2) attn_kernel() {
    extern __shared__ __align__(16) float sm[];
    float* Qs  = sm;                    // [128][68], reused as Ps
    float* Ksb = sm + 128*QST;          // [2][64][72]
    float* Vsb = Ksb + 2*KV_STG;        // [2][64][72]

    int qt = blockIdx.x, bh = blockIdx.y;
    const float* Qg = g_q + (size_t)bh*SEQ*HD;
    const float* Kg = g_k + (size_t)bh*SEQ*HD;
    const float* Vg = g_v + (size_t)bh*SEQ*HD;

    int tid = threadIdx.x, wid = tid >> 5, lane = tid & 31;
    int g = lane >> 2, t = lane & 3;
    int r0 = wid*16 + g;

    ATTN_PREFETCH(0, 0); CPCOMMIT;

    // load Q tile (already tf32 + scaled at producer)
    #pragma unroll
    for (int l = 0; l < 8; l++) {
        int idx = tid + l*256;
        int row = idx >> 4, cf = idx & 15;
        *(float4*)&Qs[row*QST + cf*4] =
            *(const float4*)(Qg + ((size_t)(qt*128+row))*HD + cf*4);
    }
    __syncthreads();

    unsigned qf[8][4];
    #pragma unroll
    for (int kk = 0; kk < 8; kk++) {
        qf[kk][0] = __float_as_uint(Qs[r0*QST     + kk*8 + t]);
        qf[kk][1] = __float_as_uint(Qs[(r0+8)*QST + kk*8 + t]);
        qf[kk][2] = __float_as_uint(Qs[r0*QST     + kk*8 + t + 4]);
        qf[kk][3] = __float_as_uint(Qs[(r0+8)*QST + kk*8 + t + 4]);
    }

    float mr0 = -1e30f, mr1 = -1e30f, lr0 = 0.0f, lr1 = 0.0f;
    float O[8][4];
    #pragma unroll
    for (int dt = 0; dt < 8; dt++)
        #pragma unroll
        for (int r = 0; r < 4; r++) O[dt][r] = 0.0f;

    for (int kt = 0; kt < SEQ/64; kt++) {
        CPWAIT0;
        __syncthreads();               // stage kt visible; everyone done with stage kt^1
        if (kt + 1 < SEQ/64) { ATTN_PREFETCH(kt+1, (kt+1)&1); }
        CPCOMMIT;

        int st = kt & 1;
        const float* Ks = Ksb + st*KV_STG;
        const float* Vs = Vsb + st*KV_STG;

        // S = Q K^T (per warp 16x64)
        float s[8][4];
        #pragma unroll
        for (int nt = 0; nt < 8; nt++)
            #pragma unroll
            for (int r = 0; r < 4; r++) s[nt][r] = 0.0f;
        #pragma unroll
        for (int kk = 0; kk < 8; kk++) {
            #pragma unroll
            for (int nt = 0; nt < 8; nt++) {
                unsigned bf[2];
                bf[0] = __float_as_uint(Ks[(nt*8+g)*KST + kk*8 + t]);
                bf[1] = __float_as_uint(Ks[(nt*8+g)*KST + kk*8 + t + 4]);
                mma8(s[nt], qf[kk], bf);
            }
        }

        // online softmax
        float rm0 = -1e30f, rm1 = -1e30f;
        #pragma unroll
        for (int nt = 0; nt < 8; nt++) {
            rm0 = fmaxf(rm0, fmaxf(s[nt][0], s[nt][1]));
            rm1 = fmaxf(rm1, fmaxf(s[nt][2], s[nt][3]));
        }
        rm0 = fmaxf(rm0, __shfl_xor_sync(0xffffffffu, rm0, 1));
        rm0 = fmaxf(rm0, __shfl_xor_sync(0xffffffffu, rm0, 2));
        rm1 = fmaxf(rm1, __shfl_xor_sync(0xffffffffu, rm1, 1));
        rm1 = fmaxf(rm1, __shfl_xor_sync(0xffffffffu, rm1, 2));
        float mn0 = fmaxf(mr0, rm0), mn1 = fmaxf(mr1, rm1);
        float a0 = __expf(mr0 - mn0), a1 = __expf(mr1 - mn1);
        mr0 = mn0; mr1 = mn1;
        float rs0 = 0.0f, rs1 = 0.0f;
        #pragma unroll
        for (int nt = 0; nt < 8; nt++) {
            s[nt][0] = __expf(s[nt][0] - mn0); rs0 += s[nt][0];
            s[nt][1] = __expf(s[nt][1] - mn0); rs0 += s[nt][1];
            s[nt][2] = __expf(s[nt][2] - mn1); rs1 += s[nt][2];
            s[nt][3] = __expf(s[nt][3] - mn1); rs1 += s[nt][3];
        }
        rs0 += __shfl_xor_sync(0xffffffffu, rs0, 1);
        rs0 += __shfl_xor_sync(0xffffffffu, rs0, 2);
        rs1 += __shfl_xor_sync(0xffffffffu, rs1, 1);
        rs1 += __shfl_xor_sync(0xffffffffu, rs1, 2);
        lr0 = lr0*a0 + rs0; lr1 = lr1*a1 + rs1;
        #pragma unroll
        for (int dt = 0; dt < 8; dt++) {
            O[dt][0] *= a0; O[dt][1] *= a0;
            O[dt][2] *= a1; O[dt][3] *= a1;
        }

        // store P (tf32) to warp-private rows of Qs
        float* Ps = Qs;
        #pragma unroll
        for (int nt = 0; nt < 8; nt++) {
            float2 p0 = make_float2(f2tff(s[nt][0]), f2tff(s[nt][1]));
            float2 p1 = make_float2(f2tff(s[nt][2]), f2tff(s[nt][3]));
            *(float2*)&Ps[r0*QST     + nt*8 + 2*t] = p0;
            *(float2*)&Ps[(r0+8)*QST + nt*8 + 2*t] = p1;
        }
        __syncwarp();

        // O += P V
        #pragma unroll
        for (int jj = 0; jj < 8; jj++) {
            unsigned af[4];
            af[0] = __float_as_uint(Qs[r0*QST     + jj*8 + t]);
            af[1] = __float_as_uint(Qs[(r0+8)*QST + jj*8 + t]);
            af[2] = __float_as_uint(Qs[r0*QST     + jj*8 + t + 4]);
            af[3] = __float_as_uint(Qs[(r0+8)*QST + jj*8 + t + 4]);
            #pragma unroll
            for (int dt = 0; dt < 8; dt++) {
                unsigned bf[2];
                bf[0] = __float_as_uint(Vs[(jj*8+t  )*KST + dt*8 + g]);
                bf[1] = __float_as_uint(Vs[(jj*8+t+4)*KST + dt*8 + g]);
                mma8(O[dt], af, bf);
            }
        }
    }

    // epilogue: normalize, tf32-round, write [B,N,D]
    int b = bh / NH, h = bh - b*NH;
    float inv0 = 1.0f/lr0, inv1 = 1.0f/lr1;
    int n = qt*128 + r0;
    #pragma unroll
    for (int dt = 0; dt < 8; dt++) {
        int d = h*HD + dt*8 + 2*t;
        float2 va = make_float2(f2tff(O[dt][0]*inv0), f2tff(O[dt][1]*inv0));
        float2 vb = make_float2(f2tff(O[dt][2]*inv1), f2tff(O[dt][3]*inv1));
        *(float2*)(g_att + ((size_t)(b*SEQ + n))*DIM + d) = va;
        *(float2*)(g_att + ((size_t)(b*SEQ + n + 8))*DIM + d) = vb;
    }
}

// ---------------- launch ----------------
extern "C" void kernel_launch(void* const* d_in, const int* in_sizes, int n_in,
                              void* d_out, int out_size) {
    const float* x     = (const float*)d_in[0];
    const float* gamma = (const float*)d_in[1];
    const float* beta  = (const float*)d_in[2];
    const float* Wqkv  = (const float*)d_in[3];
    const float* bqkv  = (const float*)d_in[4];
    const float* Wout  = (const float*)d_in[5];
    const float* bout  = (const float*)d_in[6];
    float* out = (float*)d_out;

    cudaFuncSetAttribute(gemm_kernel<1>, cudaFuncAttributeMaxDynamicSharedMemorySize, GEMM_SMEM);
    cudaFuncSetAttribute(gemm_kernel<0>, cudaFuncAttributeMaxDynamicSharedMemorySize, GEMM_SMEM);
    cudaFuncSetAttribute(attn_kernel,    cudaFuncAttributeMaxDynamicSharedMemorySize, ATTN_SMEM);

    wcvt_kernel<<<(DIM*3*DIM/4 + 255)/256, 256>>>((const float4*)Wqkv, DIM*3*DIM/4, 0);
    wcvt_kernel<<<(DIM*DIM/4   + 255)/256, 256>>>((const float4*)Wout, DIM*DIM/4,   1);

    ln_kernel<<<ROWS, 256>>>(x, gamma, beta);

    gemm_kernel<1><<<dim3((3*DIM)/128, ROWS/128), 256, GEMM_SMEM>>>(bqkv, nullptr, 3*DIM);

    attn_kernel<<<dim3(SEQ/128, BATCH*NH), 256, ATTN_SMEM>>>();

    gemm_kernel<0><<<dim3(DIM/128, ROWS/128), 256, GEMM_SMEM>>>(bout, out, DIM);
}